// round 2
// baseline (speedup 1.0000x reference)
#include <cuda_runtime.h>
#include <stdint.h>

#define NN 100000
#define NE 3200000
#define NF 512
#define ND 64
#define NC 10

// ---- scratch (no allocations allowed) ----
__device__ __align__(16) float g_h[(size_t)NN * ND];     // 25.6 MB
__device__ __align__(16) float g_agg[(size_t)NN * ND];   // 25.6 MB
__device__ float g_deg[NN];
__device__ float g_dinv[NN];
__device__ __align__(16) float g_Wm1[NF * ND];           // 128 KB
__device__ __align__(16) float g_Wm2t[NC * ND];          // transposed [c][j]

// ---------------------------------------------------------------------------
// K0: masked weights + zero degree
// ---------------------------------------------------------------------------
__global__ void prep_kernel(const float* __restrict__ W1, const float* __restrict__ M1,
                            const float* __restrict__ W2, const float* __restrict__ M2) {
    int idx = blockIdx.x * blockDim.x + threadIdx.x;
    if (idx < NF * ND) g_Wm1[idx] = W1[idx] * M1[idx];
    if (idx < ND * NC) {
        int j = idx / NC, c = idx % NC;
        g_Wm2t[c * ND + j] = W2[idx] * M2[idx];
    }
    if (idx < NN) g_deg[idx] = 0.0f;
}

// ---------------------------------------------------------------------------
// K1: weighted in-degree (edges only; self-loop +1 folded into dinv)
// edge_index is int32 (JAX x64-disabled downcasts int64 -> int32)
// ---------------------------------------------------------------------------
__global__ void deg_kernel(const int* __restrict__ ei, const float* __restrict__ ew) {
    int e = blockIdx.x * blockDim.x + threadIdx.x;
    if (e >= NE) return;
    int dst = ei[NE + e];
    atomicAdd(&g_deg[dst], ew[e]);
}

// ---------------------------------------------------------------------------
// K2: dinv = rsqrt(deg + 1)
// ---------------------------------------------------------------------------
__global__ void dinv_kernel() {
    int i = blockIdx.x * blockDim.x + threadIdx.x;
    if (i >= NN) return;
    g_dinv[i] = rsqrtf(g_deg[i] + 1.0f);
}

// ---------------------------------------------------------------------------
// K3: h = x @ Wm1   [100000,512] @ [512,64]
// Block tile: 64 rows x 64 cols, 256 threads, 4x4 register micro-tile.
// ---------------------------------------------------------------------------
__global__ __launch_bounds__(256) void gemm1_kernel(const float* __restrict__ x) {
    __shared__ float xs[64][64];   // [row][k]
    __shared__ float ws[64][64];   // [k][j]

    int block_row = blockIdx.x * 64;
    int tid = threadIdx.x;
    int tx = tid & 15;             // col group (4 cols)
    int ty = tid >> 4;             // row group (4 rows)

    float acc[4][4];
#pragma unroll
    for (int i = 0; i < 4; i++)
#pragma unroll
        for (int j = 0; j < 4; j++) acc[i][j] = 0.0f;

    for (int k0 = 0; k0 < NF; k0 += 64) {
#pragma unroll
        for (int it = 0; it < 4; it++) {
            int slot = tid + it * 256;          // 0..1023 float4 slots
            int r = slot >> 4;                  // 0..63
            int q = slot & 15;                  // float4 index
            // x tile
            float4 v = make_float4(0.f, 0.f, 0.f, 0.f);
            int grow = block_row + r;
            if (grow < NN)
                v = *(const float4*)&x[(size_t)grow * NF + k0 + q * 4];
            *(float4*)&xs[r][q * 4] = v;
            // W tile
            *(float4*)&ws[r][q * 4] = *(const float4*)&g_Wm1[(k0 + r) * ND + q * 4];
        }
        __syncthreads();

#pragma unroll
        for (int kk = 0; kk < 64; kk += 4) {
            float a[4][4], b[4][4];
#pragma unroll
            for (int i = 0; i < 4; i++)
                *(float4*)&a[i][0] = *(const float4*)&xs[ty * 4 + i][kk];
#pragma unroll
            for (int t = 0; t < 4; t++)
                *(float4*)&b[t][0] = *(const float4*)&ws[kk + t][tx * 4];
#pragma unroll
            for (int t = 0; t < 4; t++)
#pragma unroll
                for (int i = 0; i < 4; i++)
#pragma unroll
                    for (int j = 0; j < 4; j++)
                        acc[i][j] += a[i][t] * b[t][j];
        }
        __syncthreads();
    }

#pragma unroll
    for (int i = 0; i < 4; i++) {
        int grow = block_row + ty * 4 + i;
        if (grow < NN)
            *(float4*)&g_h[(size_t)grow * ND + tx * 4] =
                make_float4(acc[i][0], acc[i][1], acc[i][2], acc[i][3]);
    }
}

// ---------------------------------------------------------------------------
// K4: agg[i] = h[i] * dinv[i]^2   (self-loop contribution, also zero-inits agg)
// ---------------------------------------------------------------------------
__global__ void init_agg_kernel() {
    int idx = blockIdx.x * blockDim.x + threadIdx.x;   // over NN*16 float4s
    if (idx >= NN * (ND / 4)) return;
    int i = idx >> 4;
    float di = g_dinv[i];
    float s = di * di;
    float4 h4 = *(const float4*)&g_h[(size_t)idx * 4];
    float4 v = make_float4(h4.x * s, h4.y * s, h4.z * s, h4.w * s);
    *(float4*)&g_agg[(size_t)idx * 4] = v;
}

// ---------------------------------------------------------------------------
// K5: edge scatter: agg[dst] += h[src] * (dinv[src]*w*dinv[dst])
// 16 lanes per edge, one float4 vector-reduction per lane.
// ---------------------------------------------------------------------------
__global__ void scatter_kernel(const int* __restrict__ ei, const float* __restrict__ ew) {
    long long t = (long long)blockIdx.x * blockDim.x + threadIdx.x;
    int e = (int)(t >> 4);
    int q = (int)(t & 15);
    if (e >= NE) return;
    int src = ei[e];
    int dst = ei[NE + e];
    float norm = g_dinv[src] * ew[e] * g_dinv[dst];
    float4 h4 = *(const float4*)&g_h[(size_t)src * ND + q * 4];
    float4 v = make_float4(h4.x * norm, h4.y * norm, h4.z * norm, h4.w * norm);
    float* p = &g_agg[(size_t)dst * ND + q * 4];
    asm volatile("red.global.add.v4.f32 [%0], {%1, %2, %3, %4};"
                 :: "l"(p), "f"(v.x), "f"(v.y), "f"(v.z), "f"(v.w)
                 : "memory");
}

// ---------------------------------------------------------------------------
// K6: logits = relu(agg + b1) @ Wm2 + b2
// one thread per node
// ---------------------------------------------------------------------------
__global__ __launch_bounds__(256) void gemm2_kernel(const float* __restrict__ b1,
                                                    const float* __restrict__ b2,
                                                    float* __restrict__ out) {
    __shared__ float w2t[NC][ND];
    __shared__ float b1s[ND];
    __shared__ float b2s[NC];
    int tid = threadIdx.x;
    for (int k = tid; k < NC * ND; k += blockDim.x) ((float*)w2t)[k] = g_Wm2t[k];
    if (tid < ND) b1s[tid] = b1[tid];
    if (tid < NC) b2s[tid] = b2[tid];
    __syncthreads();

    int i = blockIdx.x * blockDim.x + tid;
    if (i >= NN) return;

    float acc[NC];
#pragma unroll
    for (int c = 0; c < NC; c++) acc[c] = b2s[c];

#pragma unroll
    for (int q = 0; q < ND / 4; q++) {
        float4 h4 = *(const float4*)&g_agg[(size_t)i * ND + q * 4];
        float4 bb = *(const float4*)&b1s[q * 4];
        float4 z = make_float4(fmaxf(h4.x + bb.x, 0.f), fmaxf(h4.y + bb.y, 0.f),
                               fmaxf(h4.z + bb.z, 0.f), fmaxf(h4.w + bb.w, 0.f));
#pragma unroll
        for (int c = 0; c < NC; c++) {
            float4 w = *(const float4*)&w2t[c][q * 4];
            acc[c] += z.x * w.x + z.y * w.y + z.z * w.z + z.w * w.w;
        }
    }
#pragma unroll
    for (int c = 0; c < NC; c++) out[(size_t)i * NC + c] = acc[c];
}

// ---------------------------------------------------------------------------
// launch
// inputs: 0:x 1:edge_index 2:edge_weight 3:W1 4:M1 5:b1 6:W2 7:M2 8:b2
// ---------------------------------------------------------------------------
extern "C" void kernel_launch(void* const* d_in, const int* in_sizes, int n_in,
                              void* d_out, int out_size) {
    const float* x  = (const float*)d_in[0];
    const int*   ei = (const int*)d_in[1];
    const float* ew = (const float*)d_in[2];
    const float* W1 = (const float*)d_in[3];
    const float* M1 = (const float*)d_in[4];
    const float* b1 = (const float*)d_in[5];
    const float* W2 = (const float*)d_in[6];
    const float* M2 = (const float*)d_in[7];
    const float* b2 = (const float*)d_in[8];
    float* out = (float*)d_out;

    prep_kernel<<<(NN + 255) / 256, 256>>>(W1, M1, W2, M2);
    deg_kernel<<<(NE + 255) / 256, 256>>>(ei, ew);
    dinv_kernel<<<(NN + 255) / 256, 256>>>();
    gemm1_kernel<<<(NN + 63) / 64, 256>>>(x);
    init_agg_kernel<<<(NN * (ND / 4) + 255) / 256, 256>>>();
    scatter_kernel<<<(int)(((long long)NE * 16 + 255) / 256), 256>>>(ei, ew);
    gemm2_kernel<<<(NN + 255) / 256, 256>>>(b1, b2, out);
}

// round 4
// speedup vs baseline: 1.0671x; 1.0671x over previous
#include <cuda_runtime.h>
#include <stdint.h>

#define NN 100000
#define NE 3200000
#define NF 512
#define ND 64
#define NC 10
#define NB 391          // ceil(NN/256) scan blocks

// ---- scratch (no allocations allowed) ----
__device__ __align__(16) float g_h[(size_t)NN * ND];     // 25.6 MB
__device__ float g_deg[NN];
__device__ float g_dinv[NN];
__device__ int   g_cnt[NN];
__device__ int   g_fill[NN];
__device__ int   g_rowptr[NN];
__device__ int   g_part[512];
__device__ int   g_esrc[NE];                              // 12.8 MB
__device__ float g_enorm[NE];                             // 12.8 MB
__device__ __align__(16) float g_Wm1[NF * ND];
__device__ __align__(16) float g_Wm2t[NC * ND];           // [c][j]

// ---------------------------------------------------------------------------
// K0: masked weights + zero deg/cnt/fill
// ---------------------------------------------------------------------------
__global__ void prep_kernel(const float* __restrict__ W1, const float* __restrict__ M1,
                            const float* __restrict__ W2, const float* __restrict__ M2) {
    int idx = blockIdx.x * blockDim.x + threadIdx.x;
    if (idx < NF * ND) g_Wm1[idx] = W1[idx] * M1[idx];
    if (idx < ND * NC) {
        int j = idx / NC, c = idx % NC;
        g_Wm2t[c * ND + j] = W2[idx] * M2[idx];
    }
    if (idx < NN) { g_deg[idx] = 0.0f; g_cnt[idx] = 0; g_fill[idx] = 0; }
}

// ---------------------------------------------------------------------------
// K1: weighted in-degree + integer in-degree count
// ---------------------------------------------------------------------------
__global__ void count_deg_kernel(const int* __restrict__ ei, const float* __restrict__ ew) {
    int e = blockIdx.x * blockDim.x + threadIdx.x;
    if (e >= NE) return;
    int dst = ei[NE + e];
    atomicAdd(&g_deg[dst], ew[e]);
    atomicAdd(&g_cnt[dst], 1);
}

// ---------------------------------------------------------------------------
// K2: dinv = rsqrt(deg + 1)   (self-loop weight folded in)
// ---------------------------------------------------------------------------
__global__ void dinv_kernel() {
    int i = blockIdx.x * blockDim.x + threadIdx.x;
    if (i >= NN) return;
    g_dinv[i] = rsqrtf(g_deg[i] + 1.0f);
}

// ---------------------------------------------------------------------------
// scan: 3-kernel exclusive scan of g_cnt -> g_rowptr
// ---------------------------------------------------------------------------
__global__ void scan1_kernel() {   // per-block sums
    __shared__ int sh[256];
    int tid = threadIdx.x;
    int i = blockIdx.x * 256 + tid;
    int v = (i < NN) ? g_cnt[i] : 0;
    sh[tid] = v; __syncthreads();
    for (int off = 1; off < 256; off <<= 1) {
        int t = (tid >= off) ? sh[tid - off] : 0;
        __syncthreads();
        sh[tid] += t; __syncthreads();
    }
    if (tid == 255) g_part[blockIdx.x] = sh[255];
}

__global__ void scan2_kernel() {   // exclusive scan of NB partials (1 block, 512 thr)
    __shared__ int sh[512];
    int tid = threadIdx.x;
    int v = (tid < NB) ? g_part[tid] : 0;
    sh[tid] = v; __syncthreads();
    for (int off = 1; off < 512; off <<= 1) {
        int t = (tid >= off) ? sh[tid - off] : 0;
        __syncthreads();
        sh[tid] += t; __syncthreads();
    }
    if (tid < NB) g_part[tid] = sh[tid] - v;  // exclusive
}

__global__ void scan3_kernel() {   // block exclusive scan + offset
    __shared__ int sh[256];
    int tid = threadIdx.x;
    int i = blockIdx.x * 256 + tid;
    int v = (i < NN) ? g_cnt[i] : 0;
    sh[tid] = v; __syncthreads();
    for (int off = 1; off < 256; off <<= 1) {
        int t = (tid >= off) ? sh[tid - off] : 0;
        __syncthreads();
        sh[tid] += t; __syncthreads();
    }
    if (i < NN) g_rowptr[i] = sh[tid] - v + g_part[blockIdx.x];
}

// ---------------------------------------------------------------------------
// K3: bucket fill: per edge store (src, norm) into dst's CSR segment
// ---------------------------------------------------------------------------
__global__ void fill_kernel(const int* __restrict__ ei, const float* __restrict__ ew) {
    int e = blockIdx.x * blockDim.x + threadIdx.x;
    if (e >= NE) return;
    int src = ei[e];
    int dst = ei[NE + e];
    float nm = g_dinv[src] * ew[e] * g_dinv[dst];
    int pos = g_rowptr[dst] + atomicAdd(&g_fill[dst], 1);
    g_esrc[pos]  = src;
    g_enorm[pos] = nm;
}

// ---------------------------------------------------------------------------
// K4: h = x @ Wm1   [100000,512] @ [512,64]
// Block tile: 128 rows x 64 cols, 256 threads, 8x4 register micro-tile.
// ---------------------------------------------------------------------------
__global__ __launch_bounds__(256) void gemm1_kernel(const float* __restrict__ x) {
    __shared__ float xs[128][68];  // [row][k], pad to 68 (16B-aligned rows)
    __shared__ float ws[64][64];   // [k][j]

    int block_row = blockIdx.x * 128;
    int tid = threadIdx.x;
    int tx = tid & 15;             // col group (4 cols)
    int ty = tid >> 4;             // row group (8 rows)

    float acc[8][4];
#pragma unroll
    for (int i = 0; i < 8; i++)
#pragma unroll
        for (int j = 0; j < 4; j++) acc[i][j] = 0.0f;

    for (int k0 = 0; k0 < NF; k0 += 64) {
        // load x tile: 128 rows x 16 float4 = 2048 slots, 8 per thread
#pragma unroll
        for (int it = 0; it < 8; it++) {
            int slot = tid + it * 256;
            int r = slot >> 4;         // 0..127
            int q = slot & 15;         // float4 idx
            float4 v = make_float4(0.f, 0.f, 0.f, 0.f);
            int grow = block_row + r;
            if (grow < NN)
                v = *(const float4*)&x[(size_t)grow * NF + k0 + q * 4];
            *(float4*)&xs[r][q * 4] = v;
        }
        // load W tile: 64 rows x 16 float4 = 1024 slots, 4 per thread
#pragma unroll
        for (int it = 0; it < 4; it++) {
            int slot = tid + it * 256;
            int r = slot >> 4;
            int q = slot & 15;
            *(float4*)&ws[r][q * 4] = *(const float4*)&g_Wm1[(k0 + r) * ND + q * 4];
        }
        __syncthreads();

#pragma unroll 8
        for (int kk = 0; kk < 64; kk++) {
            float b[4];
            *(float4*)&b[0] = *(const float4*)&ws[kk][tx * 4];
            float a[8];
#pragma unroll
            for (int i = 0; i < 8; i++) a[i] = xs[ty * 8 + i][kk];
#pragma unroll
            for (int i = 0; i < 8; i++)
#pragma unroll
                for (int j = 0; j < 4; j++)
                    acc[i][j] += a[i] * b[j];
        }
        __syncthreads();
    }

#pragma unroll
    for (int i = 0; i < 8; i++) {
        int grow = block_row + ty * 8 + i;
        if (grow < NN)
            *(float4*)&g_h[(size_t)grow * ND + tx * 4] =
                make_float4(acc[i][0], acc[i][1], acc[i][2], acc[i][3]);
    }
}

// ---------------------------------------------------------------------------
// K5: fused gather + relu + classifier
// One warp per node: acc(float2 per lane) over in-edges, then
// logits = relu(acc + b1) @ Wm2 + b2 via warp reduction.
// ---------------------------------------------------------------------------
__global__ __launch_bounds__(256) void gather_fused_kernel(const float* __restrict__ b1,
                                                           const float* __restrict__ b2,
                                                           float* __restrict__ out) {
    __shared__ float w2t[NC][ND];
    __shared__ float b1s[ND];
    __shared__ float b2s[NC];
    int tid = threadIdx.x;
    for (int k = tid; k < NC * ND; k += 256) ((float*)w2t)[k] = g_Wm2t[k];
    if (tid < ND) b1s[tid] = b1[tid];
    if (tid < NC) b2s[tid] = b2[tid];
    __syncthreads();

    int warp = tid >> 5;
    int lane = tid & 31;
    int i = blockIdx.x * 8 + warp;
    if (i >= NN) return;

    float di = g_dinv[i];
    float sloop = di * di;
    const float2* hp = (const float2*)&g_h[(size_t)i * ND];
    float2 acc = hp[lane];
    acc.x *= sloop; acc.y *= sloop;

    int beg = g_rowptr[i];
    int end = beg + g_cnt[i];
    int k = beg;
    // 2-edge unrolled accumulation for MLP
    for (; k + 1 < end; k += 2) {
        int s0 = g_esrc[k],     s1 = g_esrc[k + 1];
        float n0 = g_enorm[k],  n1 = g_enorm[k + 1];
        float2 h0 = ((const float2*)&g_h[(size_t)s0 * ND])[lane];
        float2 h1 = ((const float2*)&g_h[(size_t)s1 * ND])[lane];
        acc.x += h0.x * n0 + h1.x * n1;
        acc.y += h0.y * n0 + h1.y * n1;
    }
    if (k < end) {
        int s0 = g_esrc[k];
        float n0 = g_enorm[k];
        float2 h0 = ((const float2*)&g_h[(size_t)s0 * ND])[lane];
        acc.x += h0.x * n0;
        acc.y += h0.y * n0;
    }

    // relu(acc + b1)
    float zx = fmaxf(acc.x + b1s[lane * 2],     0.f);
    float zy = fmaxf(acc.y + b1s[lane * 2 + 1], 0.f);

    // classifier: out[c] = sum_j z_j * w2t[c][j]
    float p[NC];
#pragma unroll
    for (int c = 0; c < NC; c++)
        p[c] = zx * w2t[c][lane * 2] + zy * w2t[c][lane * 2 + 1];
#pragma unroll
    for (int off = 16; off > 0; off >>= 1)
#pragma unroll
        for (int c = 0; c < NC; c++)
            p[c] += __shfl_down_sync(0xFFFFFFFFu, p[c], off);

    if (lane == 0) {
#pragma unroll
        for (int c = 0; c < NC; c++)
            out[(size_t)i * NC + c] = p[c] + b2s[c];
    }
}

// ---------------------------------------------------------------------------
// launch
// inputs: 0:x 1:edge_index 2:edge_weight 3:W1 4:M1 5:b1 6:W2 7:M2 8:b2
// ---------------------------------------------------------------------------
extern "C" void kernel_launch(void* const* d_in, const int* in_sizes, int n_in,
                              void* d_out, int out_size) {
    const float* x  = (const float*)d_in[0];
    const int*   ei = (const int*)d_in[1];
    const float* ew = (const float*)d_in[2];
    const float* W1 = (const float*)d_in[3];
    const float* M1 = (const float*)d_in[4];
    const float* b1 = (const float*)d_in[5];
    const float* W2 = (const float*)d_in[6];
    const float* M2 = (const float*)d_in[7];
    const float* b2 = (const float*)d_in[8];
    float* out = (float*)d_out;

    prep_kernel<<<(NN + 255) / 256, 256>>>(W1, M1, W2, M2);
    count_deg_kernel<<<NE / 256, 256>>>(ei, ew);
    dinv_kernel<<<(NN + 255) / 256, 256>>>();
    scan1_kernel<<<NB, 256>>>();
    scan2_kernel<<<1, 512>>>();
    scan3_kernel<<<NB, 256>>>();
    fill_kernel<<<NE / 256, 256>>>(ei, ew);
    gemm1_kernel<<<(NN + 127) / 128, 256>>>(x);
    gather_fused_kernel<<<(NN + 7) / 8, 256>>>(b1, b2, out);
}

// round 7
// speedup vs baseline: 1.3848x; 1.2977x over previous
#include <cuda_runtime.h>
#include <cuda_bf16.h>
#include <stdint.h>

#define NN 100000
#define NE 3200000
#define NF 512
#define ND 64
#define NC 10
#define NB 391          // ceil(NN/256) scan blocks

// ---- scratch (no allocations allowed) ----
__device__ __align__(16) float g_h[(size_t)NN * ND];     // 25.6 MB
__device__ float g_deg[NN];
__device__ float g_dinv[NN];
__device__ int   g_cnt[NN];
__device__ int   g_fill[NN];
__device__ int   g_rowptr[NN];
__device__ int   g_part[512];
__device__ int   g_esrc[NE];                              // 12.8 MB
__device__ float g_enorm[NE];                             // 12.8 MB
__device__ __align__(16) __nv_bfloat16 g_W1bh[NF * ND];   // [k][n] bf16 hi
__device__ __align__(16) __nv_bfloat16 g_W1bl[NF * ND];   // [k][n] bf16 lo
__device__ __align__(16) float g_Wm2t[NC * ND];           // [c][j]

// ===========================================================================
// warp-MMA helpers (baseline PTX: works on plain sm_103 target)
// ===========================================================================
__device__ __forceinline__ uint32_t smem_to_u32(const void* p) {
    uint32_t a;
    asm("{ .reg .u64 t; cvta.to.shared.u64 t, %1; cvt.u32.u64 %0, t; }" : "=r"(a) : "l"(p));
    return a;
}
__device__ __forceinline__ void ldm_x4(uint32_t* r, uint32_t a) {
    asm volatile("ldmatrix.sync.aligned.m8n8.x4.shared.b16 {%0,%1,%2,%3}, [%4];"
                 : "=r"(r[0]), "=r"(r[1]), "=r"(r[2]), "=r"(r[3]) : "r"(a));
}
__device__ __forceinline__ void ldm_x2t(uint32_t* r, uint32_t a) {
    asm volatile("ldmatrix.sync.aligned.m8n8.x2.trans.shared.b16 {%0,%1}, [%2];"
                 : "=r"(r[0]), "=r"(r[1]) : "r"(a));
}
__device__ __forceinline__ void mma_bf16(float* c, const uint32_t* a, const uint32_t* b) {
    asm volatile("mma.sync.aligned.m16n8k16.row.col.f32.bf16.bf16.f32 "
                 "{%0,%1,%2,%3}, {%4,%5,%6,%7}, {%8,%9}, {%0,%1,%2,%3};"
                 : "+f"(c[0]), "+f"(c[1]), "+f"(c[2]), "+f"(c[3])
                 : "r"(a[0]), "r"(a[1]), "r"(a[2]), "r"(a[3]), "r"(b[0]), "r"(b[1]));
}

// ---------------------------------------------------------------------------
// K0: W2 mask/transpose + zero deg/cnt/fill
// ---------------------------------------------------------------------------
__global__ void prep_kernel(const float* __restrict__ W2, const float* __restrict__ M2) {
    int idx = blockIdx.x * blockDim.x + threadIdx.x;
    if (idx < ND * NC) {
        int j = idx / NC, c = idx % NC;
        g_Wm2t[c * ND + j] = W2[idx] * M2[idx];
    }
    if (idx < NN) { g_deg[idx] = 0.0f; g_cnt[idx] = 0; g_fill[idx] = 0; }
}

// K0b: W1 masked -> bf16 hi/lo split, layout stays [k][n]
__global__ void prep_w1_kernel(const float* __restrict__ W1, const float* __restrict__ M1) {
    int idx = blockIdx.x * blockDim.x + threadIdx.x;   // over NF*ND
    if (idx >= NF * ND) return;
    float w = W1[idx] * M1[idx];
    __nv_bfloat16 hi = __float2bfloat16(w);
    float r = w - __bfloat162float(hi);
    g_W1bh[idx] = hi;
    g_W1bl[idx] = __float2bfloat16(r);
}

// ---------------------------------------------------------------------------
// K1: weighted in-degree + integer in-degree count
// ---------------------------------------------------------------------------
__global__ void count_deg_kernel(const int* __restrict__ ei, const float* __restrict__ ew) {
    int e = blockIdx.x * blockDim.x + threadIdx.x;
    if (e >= NE) return;
    int dst = ei[NE + e];
    atomicAdd(&g_deg[dst], ew[e]);
    atomicAdd(&g_cnt[dst], 1);
}

__global__ void dinv_kernel() {
    int i = blockIdx.x * blockDim.x + threadIdx.x;
    if (i >= NN) return;
    g_dinv[i] = rsqrtf(g_deg[i] + 1.0f);
}

// ---------------------------------------------------------------------------
// 3-kernel exclusive scan of g_cnt -> g_rowptr
// ---------------------------------------------------------------------------
__global__ void scan1_kernel() {
    __shared__ int sh[256];
    int tid = threadIdx.x;
    int i = blockIdx.x * 256 + tid;
    int v = (i < NN) ? g_cnt[i] : 0;
    sh[tid] = v; __syncthreads();
    for (int off = 1; off < 256; off <<= 1) {
        int t = (tid >= off) ? sh[tid - off] : 0;
        __syncthreads();
        sh[tid] += t; __syncthreads();
    }
    if (tid == 255) g_part[blockIdx.x] = sh[255];
}

__global__ void scan2_kernel() {
    __shared__ int sh[512];
    int tid = threadIdx.x;
    int v = (tid < NB) ? g_part[tid] : 0;
    sh[tid] = v; __syncthreads();
    for (int off = 1; off < 512; off <<= 1) {
        int t = (tid >= off) ? sh[tid - off] : 0;
        __syncthreads();
        sh[tid] += t; __syncthreads();
    }
    if (tid < NB) g_part[tid] = sh[tid] - v;
}

__global__ void scan3_kernel() {
    __shared__ int sh[256];
    int tid = threadIdx.x;
    int i = blockIdx.x * 256 + tid;
    int v = (i < NN) ? g_cnt[i] : 0;
    sh[tid] = v; __syncthreads();
    for (int off = 1; off < 256; off <<= 1) {
        int t = (tid >= off) ? sh[tid - off] : 0;
        __syncthreads();
        sh[tid] += t; __syncthreads();
    }
    if (i < NN) g_rowptr[i] = sh[tid] - v + g_part[blockIdx.x];
}

// ---------------------------------------------------------------------------
// K3: bucket fill
// ---------------------------------------------------------------------------
__global__ void fill_kernel(const int* __restrict__ ei, const float* __restrict__ ew) {
    int e = blockIdx.x * blockDim.x + threadIdx.x;
    if (e >= NE) return;
    int src = ei[e];
    int dst = ei[NE + e];
    float nm = g_dinv[src] * ew[e] * g_dinv[dst];
    int pos = g_rowptr[dst] + atomicAdd(&g_fill[dst], 1);
    g_esrc[pos]  = src;
    g_enorm[pos] = nm;
}

// ---------------------------------------------------------------------------
// K4: h = x @ (W1*M1) via mma.sync bf16 with 2-term hi/lo split (3 mmas).
// Block: 128 rows x 64 cols, 8 warps (one m16 slab each), K-chunks of 64.
// ---------------------------------------------------------------------------
#define MBLK 128
#define XST 72                       // smem row stride (bf16 elems) = 144 B
#define OFF_XH 0
#define OFF_XL (MBLK * XST)
#define OFF_WH (OFF_XL + MBLK * XST)
#define OFF_WL (OFF_WH + 64 * XST)
#define SMEM_ELEMS (OFF_WL + 64 * XST)
#define SMEM_BYTES (SMEM_ELEMS * 2)

__global__ __launch_bounds__(256) void gemm1_mma(const float* __restrict__ x) {
    extern __shared__ __align__(16) __nv_bfloat16 sm[];
    uint32_t sb = smem_to_u32(sm);
    int tid = threadIdx.x;
    int wid = tid >> 5;
    int lane = tid & 31;
    int brow = blockIdx.x * MBLK;
    int m0 = wid * 16;

    float acc[8][4];
#pragma unroll
    for (int nb = 0; nb < 8; nb++)
#pragma unroll
        for (int j = 0; j < 4; j++) acc[nb][j] = 0.0f;

    for (int kc = 0; kc < NF; kc += 64) {
        // --- x tile: 128 rows x 64 cols fp32 -> bf16 hi/lo ---
#pragma unroll
        for (int it = 0; it < 8; it++) {
            int slot = tid + it * 256;      // 0..2047
            int r = slot >> 4;              // 0..127
            int q = slot & 15;              // float4 idx
            float4 v = make_float4(0.f, 0.f, 0.f, 0.f);
            int grow = brow + r;
            if (grow < NN)
                v = *(const float4*)&x[(size_t)grow * NF + kc + q * 4];
            __nv_bfloat16 hx = __float2bfloat16(v.x), hy = __float2bfloat16(v.y);
            __nv_bfloat16 hz = __float2bfloat16(v.z), hw = __float2bfloat16(v.w);
            __nv_bfloat162 h0; h0.x = hx; h0.y = hy;
            __nv_bfloat162 h1; h1.x = hz; h1.y = hw;
            __nv_bfloat162 l0, l1;
            l0.x = __float2bfloat16(v.x - __bfloat162float(hx));
            l0.y = __float2bfloat16(v.y - __bfloat162float(hy));
            l1.x = __float2bfloat16(v.z - __bfloat162float(hz));
            l1.y = __float2bfloat16(v.w - __bfloat162float(hw));
            *(uint2*)&sm[OFF_XH + r * XST + q * 4] = make_uint2(*(uint32_t*)&h0, *(uint32_t*)&h1);
            *(uint2*)&sm[OFF_XL + r * XST + q * 4] = make_uint2(*(uint32_t*)&l0, *(uint32_t*)&l1);
        }
        // --- W tile: 64 k-rows x 64 n-cols bf16 (pre-split) ---
#pragma unroll
        for (int it = 0; it < 4; it++) {
            int slot = tid + it * 256;      // 0..1023
            int r = slot >> 4;              // k row 0..63
            int q = slot & 15;              // 4-elem group
            *(uint2*)&sm[OFF_WH + r * XST + q * 4] = *(const uint2*)&g_W1bh[(size_t)(kc + r) * ND + q * 4];
            *(uint2*)&sm[OFF_WL + r * XST + q * 4] = *(const uint2*)&g_W1bl[(size_t)(kc + r) * ND + q * 4];
        }
        __syncthreads();

#pragma unroll
        for (int ks = 0; ks < 4; ks++) {
            // A fragments (x4): rows m0 + lane%16, col ks*16 + (lane/16)*8
            int arow = m0 + (lane & 15);
            int acol = ks * 16 + (lane >> 4) * 8;
            uint32_t ah[4], al[4];
            ldm_x4(ah, sb + (OFF_XH + arow * XST + acol) * 2);
            ldm_x4(al, sb + (OFF_XL + arow * XST + acol) * 2);

            int brow_k = ks * 16 + (lane & 15);   // k row (lanes 0-15 used)
#pragma unroll
            for (int nb = 0; nb < 8; nb++) {
                uint32_t bh[2], bl[2];
                ldm_x2t(bh, sb + (OFF_WH + brow_k * XST + nb * 8) * 2);
                ldm_x2t(bl, sb + (OFF_WL + brow_k * XST + nb * 8) * 2);
                mma_bf16(acc[nb], ah, bh);
                mma_bf16(acc[nb], ah, bl);
                mma_bf16(acc[nb], al, bh);
            }
        }
        __syncthreads();
    }

    // store: c0,c1 -> row m0+lane/4, c2,c3 -> row +8; col = nb*8 + (lane%4)*2
    int r0 = brow + m0 + (lane >> 2);
    int r1 = r0 + 8;
    int cbase = (lane & 3) * 2;
#pragma unroll
    for (int nb = 0; nb < 8; nb++) {
        int col = nb * 8 + cbase;
        if (r0 < NN) *(float2*)&g_h[(size_t)r0 * ND + col] = make_float2(acc[nb][0], acc[nb][1]);
        if (r1 < NN) *(float2*)&g_h[(size_t)r1 * ND + col] = make_float2(acc[nb][2], acc[nb][3]);
    }
}

// ---------------------------------------------------------------------------
// K5: fused gather + relu + classifier. One warp per node.
// ---------------------------------------------------------------------------
__global__ __launch_bounds__(256) void gather_fused_kernel(const float* __restrict__ b1,
                                                           const float* __restrict__ b2,
                                                           float* __restrict__ out) {
    __shared__ float w2t[NC][ND];
    __shared__ float b1s[ND];
    __shared__ float b2s[NC];
    int tid = threadIdx.x;
    for (int k = tid; k < NC * ND; k += 256) ((float*)w2t)[k] = g_Wm2t[k];
    if (tid < ND) b1s[tid] = b1[tid];
    if (tid < NC) b2s[tid] = b2[tid];
    __syncthreads();

    int warp = tid >> 5;
    int lane = tid & 31;
    int i = blockIdx.x * 8 + warp;
    if (i >= NN) return;

    float di = g_dinv[i];
    float sloop = di * di;
    float2 self = ((const float2*)&g_h[(size_t)i * ND])[lane];
    float2 acc0 = make_float2(self.x * sloop, self.y * sloop);
    float2 acc1 = make_float2(0.f, 0.f);

    int beg = g_rowptr[i];
    int end = beg + g_cnt[i];
    int k = beg;
    for (; k + 3 < end; k += 4) {
        int s0 = g_esrc[k],     s1 = g_esrc[k + 1];
        int s2 = g_esrc[k + 2], s3 = g_esrc[k + 3];
        float n0 = g_enorm[k],     n1 = g_enorm[k + 1];
        float n2 = g_enorm[k + 2], n3 = g_enorm[k + 3];
        float2 h0 = ((const float2*)&g_h[(size_t)s0 * ND])[lane];
        float2 h1 = ((const float2*)&g_h[(size_t)s1 * ND])[lane];
        float2 h2 = ((const float2*)&g_h[(size_t)s2 * ND])[lane];
        float2 h3 = ((const float2*)&g_h[(size_t)s3 * ND])[lane];
        acc0.x += h0.x * n0 + h1.x * n1;
        acc0.y += h0.y * n0 + h1.y * n1;
        acc1.x += h2.x * n2 + h3.x * n3;
        acc1.y += h2.y * n2 + h3.y * n3;
    }
    for (; k < end; k++) {
        int s0 = g_esrc[k];
        float n0 = g_enorm[k];
        float2 h0 = ((const float2*)&g_h[(size_t)s0 * ND])[lane];
        acc0.x += h0.x * n0;
        acc0.y += h0.y * n0;
    }
    acc0.x += acc1.x; acc0.y += acc1.y;

    float zx = fmaxf(acc0.x + b1s[lane * 2],     0.f);
    float zy = fmaxf(acc0.y + b1s[lane * 2 + 1], 0.f);

    float p[NC];
#pragma unroll
    for (int c = 0; c < NC; c++)
        p[c] = zx * w2t[c][lane * 2] + zy * w2t[c][lane * 2 + 1];
#pragma unroll
    for (int off = 16; off > 0; off >>= 1)
#pragma unroll
        for (int c = 0; c < NC; c++)
            p[c] += __shfl_down_sync(0xFFFFFFFFu, p[c], off);

    if (lane == 0) {
#pragma unroll
        for (int c = 0; c < NC; c++)
            out[(size_t)i * NC + c] = p[c] + b2s[c];
    }
}

// ---------------------------------------------------------------------------
// launch: 0:x 1:edge_index 2:edge_weight 3:W1 4:M1 5:b1 6:W2 7:M2 8:b2
// ---------------------------------------------------------------------------
extern "C" void kernel_launch(void* const* d_in, const int* in_sizes, int n_in,
                              void* d_out, int out_size) {
    const float* x  = (const float*)d_in[0];
    const int*   ei = (const int*)d_in[1];
    const float* ew = (const float*)d_in[2];
    const float* W1 = (const float*)d_in[3];
    const float* M1 = (const float*)d_in[4];
    const float* b1 = (const float*)d_in[5];
    const float* W2 = (const float*)d_in[6];
    const float* M2 = (const float*)d_in[7];
    const float* b2 = (const float*)d_in[8];
    float* out = (float*)d_out;

    cudaFuncSetAttribute(gemm1_mma, cudaFuncAttributeMaxDynamicSharedMemorySize, SMEM_BYTES);

    prep_kernel<<<(NN + 255) / 256, 256>>>(W2, M2);
    prep_w1_kernel<<<(NF * ND + 255) / 256, 256>>>(W1, M1);
    count_deg_kernel<<<NE / 256, 256>>>(ei, ew);
    dinv_kernel<<<(NN + 255) / 256, 256>>>();
    scan1_kernel<<<NB, 256>>>();
    scan2_kernel<<<1, 512>>>();
    scan3_kernel<<<NB, 256>>>();
    fill_kernel<<<NE / 256, 256>>>(ei, ew);
    gemm1_mma<<<(NN + MBLK - 1) / MBLK, 256, SMEM_BYTES>>>(x);
    gather_fused_kernel<<<(NN + 7) / 8, 256>>>(b1, b2, out);
}

// round 8
// speedup vs baseline: 1.4514x; 1.0481x over previous
#include <cuda_runtime.h>
#include <cuda_bf16.h>
#include <cuda_fp16.h>
#include <stdint.h>

#define NN 100000
#define NE 3200000
#define NF 512
#define ND 64
#define NC 10
#define NB 391          // ceil(NN/256) scan blocks

// ---- scratch (no allocations allowed) ----
__device__ __align__(16) __half g_h16[(size_t)NN * ND];  // 12.8 MB (L2-resident)
__device__ float g_deg[NN];
__device__ float g_dinv[NN];
__device__ int   g_cnt[NN];
__device__ int   g_fill[NN];
__device__ int   g_rowptr[NN];
__device__ int   g_part[512];
__device__ __align__(16) int2 g_edge[NE];                 // (src, norm-bits) 25.6 MB
__device__ __align__(16) __nv_bfloat16 g_W1bh[NF * ND];   // [k][n] bf16 hi
__device__ __align__(16) __nv_bfloat16 g_W1bl[NF * ND];   // [k][n] bf16 lo
__device__ __align__(16) float g_Wm2t[NC * ND];           // [c][j]

// ===========================================================================
// warp-MMA helpers (baseline PTX: works on plain sm_103 target)
// ===========================================================================
__device__ __forceinline__ uint32_t smem_to_u32(const void* p) {
    uint32_t a;
    asm("{ .reg .u64 t; cvta.to.shared.u64 t, %1; cvt.u32.u64 %0, t; }" : "=r"(a) : "l"(p));
    return a;
}
__device__ __forceinline__ void ldm_x4(uint32_t* r, uint32_t a) {
    asm volatile("ldmatrix.sync.aligned.m8n8.x4.shared.b16 {%0,%1,%2,%3}, [%4];"
                 : "=r"(r[0]), "=r"(r[1]), "=r"(r[2]), "=r"(r[3]) : "r"(a));
}
__device__ __forceinline__ void ldm_x2t(uint32_t* r, uint32_t a) {
    asm volatile("ldmatrix.sync.aligned.m8n8.x2.trans.shared.b16 {%0,%1}, [%2];"
                 : "=r"(r[0]), "=r"(r[1]) : "r"(a));
}
__device__ __forceinline__ void mma_bf16(float* c, const uint32_t* a, const uint32_t* b) {
    asm volatile("mma.sync.aligned.m16n8k16.row.col.f32.bf16.bf16.f32 "
                 "{%0,%1,%2,%3}, {%4,%5,%6,%7}, {%8,%9}, {%0,%1,%2,%3};"
                 : "+f"(c[0]), "+f"(c[1]), "+f"(c[2]), "+f"(c[3])
                 : "r"(a[0]), "r"(a[1]), "r"(a[2]), "r"(a[3]), "r"(b[0]), "r"(b[1]));
}

// ---------------------------------------------------------------------------
// K0: W2 mask/transpose + zero deg/cnt/fill
// ---------------------------------------------------------------------------
__global__ void prep_kernel(const float* __restrict__ W2, const float* __restrict__ M2) {
    int idx = blockIdx.x * blockDim.x + threadIdx.x;
    if (idx < ND * NC) {
        int j = idx / NC, c = idx % NC;
        g_Wm2t[c * ND + j] = W2[idx] * M2[idx];
    }
    if (idx < NN) { g_deg[idx] = 0.0f; g_cnt[idx] = 0; g_fill[idx] = 0; }
}

// K0b: W1 masked -> bf16 hi/lo split, layout stays [k][n]
__global__ void prep_w1_kernel(const float* __restrict__ W1, const float* __restrict__ M1) {
    int idx = blockIdx.x * blockDim.x + threadIdx.x;   // over NF*ND
    if (idx >= NF * ND) return;
    float w = W1[idx] * M1[idx];
    __nv_bfloat16 hi = __float2bfloat16(w);
    float r = w - __bfloat162float(hi);
    g_W1bh[idx] = hi;
    g_W1bl[idx] = __float2bfloat16(r);
}

// ---------------------------------------------------------------------------
// K1: weighted in-degree + integer in-degree count
// ---------------------------------------------------------------------------
__global__ void count_deg_kernel(const int* __restrict__ ei, const float* __restrict__ ew) {
    int e = blockIdx.x * blockDim.x + threadIdx.x;
    if (e >= NE) return;
    int dst = ei[NE + e];
    atomicAdd(&g_deg[dst], ew[e]);
    atomicAdd(&g_cnt[dst], 1);
}

__global__ void dinv_kernel() {
    int i = blockIdx.x * blockDim.x + threadIdx.x;
    if (i >= NN) return;
    g_dinv[i] = rsqrtf(g_deg[i] + 1.0f);
}

// ---------------------------------------------------------------------------
// 3-kernel exclusive scan of g_cnt -> g_rowptr
// ---------------------------------------------------------------------------
__global__ void scan1_kernel() {
    __shared__ int sh[256];
    int tid = threadIdx.x;
    int i = blockIdx.x * 256 + tid;
    int v = (i < NN) ? g_cnt[i] : 0;
    sh[tid] = v; __syncthreads();
    for (int off = 1; off < 256; off <<= 1) {
        int t = (tid >= off) ? sh[tid - off] : 0;
        __syncthreads();
        sh[tid] += t; __syncthreads();
    }
    if (tid == 255) g_part[blockIdx.x] = sh[255];
}

__global__ void scan2_kernel() {
    __shared__ int sh[512];
    int tid = threadIdx.x;
    int v = (tid < NB) ? g_part[tid] : 0;
    sh[tid] = v; __syncthreads();
    for (int off = 1; off < 512; off <<= 1) {
        int t = (tid >= off) ? sh[tid - off] : 0;
        __syncthreads();
        sh[tid] += t; __syncthreads();
    }
    if (tid < NB) g_part[tid] = sh[tid] - v;
}

__global__ void scan3_kernel() {
    __shared__ int sh[256];
    int tid = threadIdx.x;
    int i = blockIdx.x * 256 + tid;
    int v = (i < NN) ? g_cnt[i] : 0;
    sh[tid] = v; __syncthreads();
    for (int off = 1; off < 256; off <<= 1) {
        int t = (tid >= off) ? sh[tid - off] : 0;
        __syncthreads();
        sh[tid] += t; __syncthreads();
    }
    if (i < NN) g_rowptr[i] = sh[tid] - v + g_part[blockIdx.x];
}

// ---------------------------------------------------------------------------
// K3: bucket fill — one packed 8B store per edge
// ---------------------------------------------------------------------------
__global__ void fill_kernel(const int* __restrict__ ei, const float* __restrict__ ew) {
    int e = blockIdx.x * blockDim.x + threadIdx.x;
    if (e >= NE) return;
    int src = ei[e];
    int dst = ei[NE + e];
    float nm = g_dinv[src] * ew[e] * g_dinv[dst];
    int pos = g_rowptr[dst] + atomicAdd(&g_fill[dst], 1);
    g_edge[pos] = make_int2(src, __float_as_int(nm));
}

// ---------------------------------------------------------------------------
// K4: h = x @ (W1*M1) via mma.sync bf16 with 2-term hi/lo split (3 mmas).
// Block: 128 rows x 64 cols, 8 warps (one m16 slab each), K-chunks of 64.
// Output stored fp16.
// ---------------------------------------------------------------------------
#define MBLK 128
#define XST 72                       // smem row stride (bf16 elems) = 144 B
#define OFF_XH 0
#define OFF_XL (MBLK * XST)
#define OFF_WH (OFF_XL + MBLK * XST)
#define OFF_WL (OFF_WH + 64 * XST)
#define SMEM_ELEMS (OFF_WL + 64 * XST)
#define SMEM_BYTES (SMEM_ELEMS * 2)

__global__ __launch_bounds__(256) void gemm1_mma(const float* __restrict__ x) {
    extern __shared__ __align__(16) __nv_bfloat16 sm[];
    uint32_t sb = smem_to_u32(sm);
    int tid = threadIdx.x;
    int wid = tid >> 5;
    int lane = tid & 31;
    int brow = blockIdx.x * MBLK;
    int m0 = wid * 16;

    float acc[8][4];
#pragma unroll
    for (int nb = 0; nb < 8; nb++)
#pragma unroll
        for (int j = 0; j < 4; j++) acc[nb][j] = 0.0f;

    for (int kc = 0; kc < NF; kc += 64) {
        // --- x tile: 128 rows x 64 cols fp32 -> bf16 hi/lo ---
#pragma unroll
        for (int it = 0; it < 8; it++) {
            int slot = tid + it * 256;      // 0..2047
            int r = slot >> 4;              // 0..127
            int q = slot & 15;              // float4 idx
            float4 v = make_float4(0.f, 0.f, 0.f, 0.f);
            int grow = brow + r;
            if (grow < NN)
                v = *(const float4*)&x[(size_t)grow * NF + kc + q * 4];
            __nv_bfloat16 hx = __float2bfloat16(v.x), hy = __float2bfloat16(v.y);
            __nv_bfloat16 hz = __float2bfloat16(v.z), hw = __float2bfloat16(v.w);
            __nv_bfloat162 h0; h0.x = hx; h0.y = hy;
            __nv_bfloat162 h1; h1.x = hz; h1.y = hw;
            __nv_bfloat162 l0, l1;
            l0.x = __float2bfloat16(v.x - __bfloat162float(hx));
            l0.y = __float2bfloat16(v.y - __bfloat162float(hy));
            l1.x = __float2bfloat16(v.z - __bfloat162float(hz));
            l1.y = __float2bfloat16(v.w - __bfloat162float(hw));
            *(uint2*)&sm[OFF_XH + r * XST + q * 4] = make_uint2(*(uint32_t*)&h0, *(uint32_t*)&h1);
            *(uint2*)&sm[OFF_XL + r * XST + q * 4] = make_uint2(*(uint32_t*)&l0, *(uint32_t*)&l1);
        }
        // --- W tile: 64 k-rows x 64 n-cols bf16 (pre-split) ---
#pragma unroll
        for (int it = 0; it < 4; it++) {
            int slot = tid + it * 256;      // 0..1023
            int r = slot >> 4;              // k row 0..63
            int q = slot & 15;              // 4-elem group
            *(uint2*)&sm[OFF_WH + r * XST + q * 4] = *(const uint2*)&g_W1bh[(size_t)(kc + r) * ND + q * 4];
            *(uint2*)&sm[OFF_WL + r * XST + q * 4] = *(const uint2*)&g_W1bl[(size_t)(kc + r) * ND + q * 4];
        }
        __syncthreads();

#pragma unroll
        for (int ks = 0; ks < 4; ks++) {
            int arow = m0 + (lane & 15);
            int acol = ks * 16 + (lane >> 4) * 8;
            uint32_t ah[4], al[4];
            ldm_x4(ah, sb + (OFF_XH + arow * XST + acol) * 2);
            ldm_x4(al, sb + (OFF_XL + arow * XST + acol) * 2);

            int brow_k = ks * 16 + (lane & 15);
#pragma unroll
            for (int nb = 0; nb < 8; nb++) {
                uint32_t bh[2], bl[2];
                ldm_x2t(bh, sb + (OFF_WH + brow_k * XST + nb * 8) * 2);
                ldm_x2t(bl, sb + (OFF_WL + brow_k * XST + nb * 8) * 2);
                mma_bf16(acc[nb], ah, bh);
                mma_bf16(acc[nb], ah, bl);
                mma_bf16(acc[nb], al, bh);
            }
        }
        __syncthreads();
    }

    // store fp16: c0,c1 -> row m0+lane/4, c2,c3 -> row +8; col = nb*8 + (lane%4)*2
    int r0 = brow + m0 + (lane >> 2);
    int r1 = r0 + 8;
    int cbase = (lane & 3) * 2;
#pragma unroll
    for (int nb = 0; nb < 8; nb++) {
        int col = nb * 8 + cbase;
        if (r0 < NN)
            *(__half2*)&g_h16[(size_t)r0 * ND + col] = __floats2half2_rn(acc[nb][0], acc[nb][1]);
        if (r1 < NN)
            *(__half2*)&g_h16[(size_t)r1 * ND + col] = __floats2half2_rn(acc[nb][2], acc[nb][3]);
    }
}

// ---------------------------------------------------------------------------
// K5: fused gather + relu + classifier. One warp per node, fp16 h rows.
// ---------------------------------------------------------------------------
__global__ __launch_bounds__(256) void gather_fused_kernel(const float* __restrict__ b1,
                                                           const float* __restrict__ b2,
                                                           float* __restrict__ out) {
    __shared__ float w2t[NC][ND];
    __shared__ float b1s[ND];
    __shared__ float b2s[NC];
    int tid = threadIdx.x;
    for (int k = tid; k < NC * ND; k += 256) ((float*)w2t)[k] = g_Wm2t[k];
    if (tid < ND) b1s[tid] = b1[tid];
    if (tid < NC) b2s[tid] = b2[tid];
    __syncthreads();

    int warp = tid >> 5;
    int lane = tid & 31;
    int i = blockIdx.x * 8 + warp;
    if (i >= NN) return;

    float di = g_dinv[i];
    float sloop = di * di;
    float2 self = __half22float2(((const __half2*)&g_h16[(size_t)i * ND])[lane]);
    float2 acc0 = make_float2(self.x * sloop, self.y * sloop);
    float2 acc1 = make_float2(0.f, 0.f);

    int beg = g_rowptr[i];
    int end = beg + g_cnt[i];
    int k = beg;
    for (; k + 3 < end; k += 4) {
        int2 e0 = g_edge[k],     e1 = g_edge[k + 1];
        int2 e2 = g_edge[k + 2], e3 = g_edge[k + 3];
        float2 h0 = __half22float2(((const __half2*)&g_h16[(size_t)e0.x * ND])[lane]);
        float2 h1 = __half22float2(((const __half2*)&g_h16[(size_t)e1.x * ND])[lane]);
        float2 h2 = __half22float2(((const __half2*)&g_h16[(size_t)e2.x * ND])[lane]);
        float2 h3 = __half22float2(((const __half2*)&g_h16[(size_t)e3.x * ND])[lane]);
        float n0 = __int_as_float(e0.y), n1 = __int_as_float(e1.y);
        float n2 = __int_as_float(e2.y), n3 = __int_as_float(e3.y);
        acc0.x += h0.x * n0 + h1.x * n1;
        acc0.y += h0.y * n0 + h1.y * n1;
        acc1.x += h2.x * n2 + h3.x * n3;
        acc1.y += h2.y * n2 + h3.y * n3;
    }
    for (; k < end; k++) {
        int2 e0 = g_edge[k];
        float2 h0 = __half22float2(((const __half2*)&g_h16[(size_t)e0.x * ND])[lane]);
        float n0 = __int_as_float(e0.y);
        acc0.x += h0.x * n0;
        acc0.y += h0.y * n0;
    }
    acc0.x += acc1.x; acc0.y += acc1.y;

    float zx = fmaxf(acc0.x + b1s[lane * 2],     0.f);
    float zy = fmaxf(acc0.y + b1s[lane * 2 + 1], 0.f);

    float p[NC];
#pragma unroll
    for (int c = 0; c < NC; c++)
        p[c] = zx * w2t[c][lane * 2] + zy * w2t[c][lane * 2 + 1];
#pragma unroll
    for (int off = 16; off > 0; off >>= 1)
#pragma unroll
        for (int c = 0; c < NC; c++)
            p[c] += __shfl_down_sync(0xFFFFFFFFu, p[c], off);

    if (lane == 0) {
#pragma unroll
        for (int c = 0; c < NC; c++)
            out[(size_t)i * NC + c] = p[c] + b2s[c];
    }
}

// ---------------------------------------------------------------------------
// launch: 0:x 1:edge_index 2:edge_weight 3:W1 4:M1 5:b1 6:W2 7:M2 8:b2
// ---------------------------------------------------------------------------
extern "C" void kernel_launch(void* const* d_in, const int* in_sizes, int n_in,
                              void* d_out, int out_size) {
    const float* x  = (const float*)d_in[0];
    const int*   ei = (const int*)d_in[1];
    const float* ew = (const float*)d_in[2];
    const float* W1 = (const float*)d_in[3];
    const float* M1 = (const float*)d_in[4];
    const float* b1 = (const float*)d_in[5];
    const float* W2 = (const float*)d_in[6];
    const float* M2 = (const float*)d_in[7];
    const float* b2 = (const float*)d_in[8];
    float* out = (float*)d_out;

    cudaFuncSetAttribute(gemm1_mma, cudaFuncAttributeMaxDynamicSharedMemorySize, SMEM_BYTES);

    prep_kernel<<<(NN + 255) / 256, 256>>>(W2, M2);
    prep_w1_kernel<<<(NF * ND + 255) / 256, 256>>>(W1, M1);
    count_deg_kernel<<<NE / 256, 256>>>(ei, ew);
    dinv_kernel<<<(NN + 255) / 256, 256>>>();
    scan1_kernel<<<NB, 256>>>();
    scan2_kernel<<<1, 512>>>();
    scan3_kernel<<<NB, 256>>>();
    fill_kernel<<<NE / 256, 256>>>(ei, ew);
    gemm1_mma<<<(NN + MBLK - 1) / MBLK, 256, SMEM_BYTES>>>(x);
    gather_fused_kernel<<<(NN + 7) / 8, 256>>>(b1, b2, out);
}

// round 9
// speedup vs baseline: 1.6721x; 1.1520x over previous
#include <cuda_runtime.h>
#include <cuda_bf16.h>
#include <cuda_fp16.h>
#include <stdint.h>

#define NN 100000
#define NE 3200000
#define NF 512
#define ND 64
#define NC 10
#define NB 391          // ceil(NN/256) scan blocks

// ---- scratch (no allocations allowed) ----
__device__ __align__(16) __half g_h16[(size_t)NN * ND];  // 12.8 MB (L2-resident)
__device__ float g_deg[NN];
__device__ float g_dinv[NN];
__device__ int   g_cnt[NN];
__device__ int   g_fill[NN];
__device__ int   g_lscan[NN];                             // block-local exclusive scan
__device__ int   g_part[512];
__device__ __align__(16) int2 g_edge[NE];                 // (src, norm-bits) 25.6 MB
__device__ __align__(16) __nv_bfloat16 g_W1bh[NF * ND];   // [k][n] bf16 hi
__device__ __align__(16) __nv_bfloat16 g_W1bl[NF * ND];   // [k][n] bf16 lo
__device__ __align__(16) float g_Wm2t[NC * ND];           // [c][j]

// ===========================================================================
// warp-MMA helpers (baseline PTX: works on plain sm_103 target)
// ===========================================================================
__device__ __forceinline__ uint32_t smem_to_u32(const void* p) {
    uint32_t a;
    asm("{ .reg .u64 t; cvta.to.shared.u64 t, %1; cvt.u32.u64 %0, t; }" : "=r"(a) : "l"(p));
    return a;
}
__device__ __forceinline__ void ldm_x4(uint32_t* r, uint32_t a) {
    asm volatile("ldmatrix.sync.aligned.m8n8.x4.shared.b16 {%0,%1,%2,%3}, [%4];"
                 : "=r"(r[0]), "=r"(r[1]), "=r"(r[2]), "=r"(r[3]) : "r"(a));
}
__device__ __forceinline__ void ldm_x2t(uint32_t* r, uint32_t a) {
    asm volatile("ldmatrix.sync.aligned.m8n8.x2.trans.shared.b16 {%0,%1}, [%2];"
                 : "=r"(r[0]), "=r"(r[1]) : "r"(a));
}
__device__ __forceinline__ void mma_bf16(float* c, const uint32_t* a, const uint32_t* b) {
    asm volatile("mma.sync.aligned.m16n8k16.row.col.f32.bf16.bf16.f32 "
                 "{%0,%1,%2,%3}, {%4,%5,%6,%7}, {%8,%9}, {%0,%1,%2,%3};"
                 : "+f"(c[0]), "+f"(c[1]), "+f"(c[2]), "+f"(c[3])
                 : "r"(a[0]), "r"(a[1]), "r"(a[2]), "r"(a[3]), "r"(b[0]), "r"(b[1]));
}

// ---------------------------------------------------------------------------
// K1: fused prep — zero deg/cnt/fill, W1 bf16 hi/lo split, W2 mask/transpose
// ---------------------------------------------------------------------------
__global__ void prep_kernel(const float* __restrict__ W1, const float* __restrict__ M1,
                            const float* __restrict__ W2, const float* __restrict__ M2) {
    int idx = blockIdx.x * blockDim.x + threadIdx.x;
    if (idx < NN) { g_deg[idx] = 0.0f; g_cnt[idx] = 0; g_fill[idx] = 0; }
    if (idx < NF * ND) {
        float w = W1[idx] * M1[idx];
        __nv_bfloat16 hi = __float2bfloat16(w);
        float r = w - __bfloat162float(hi);
        g_W1bh[idx] = hi;
        g_W1bl[idx] = __float2bfloat16(r);
    }
    if (idx < ND * NC) {
        int j = idx / NC, c = idx % NC;
        g_Wm2t[c * ND + j] = W2[idx] * M2[idx];
    }
}

// ---------------------------------------------------------------------------
// K2: weighted in-degree + integer in-degree count
// ---------------------------------------------------------------------------
__global__ void count_deg_kernel(const int* __restrict__ ei, const float* __restrict__ ew) {
    int e = blockIdx.x * blockDim.x + threadIdx.x;
    if (e >= NE) return;
    int dst = ei[NE + e];
    atomicAdd(&g_deg[dst], ew[e]);
    atomicAdd(&g_cnt[dst], 1);
}

// ---------------------------------------------------------------------------
// K3: fused dinv + block-local scan of cnt (lscan + block partials)
// ---------------------------------------------------------------------------
__global__ void dinv_scan1_kernel() {
    __shared__ int sh[256];
    int tid = threadIdx.x;
    int i = blockIdx.x * 256 + tid;
    if (i < NN) g_dinv[i] = rsqrtf(g_deg[i] + 1.0f);
    int v = (i < NN) ? g_cnt[i] : 0;
    sh[tid] = v; __syncthreads();
    for (int off = 1; off < 256; off <<= 1) {
        int t = (tid >= off) ? sh[tid - off] : 0;
        __syncthreads();
        sh[tid] += t; __syncthreads();
    }
    if (i < NN) g_lscan[i] = sh[tid] - v;        // block-local exclusive
    if (tid == 255) g_part[blockIdx.x] = sh[255];
}

// K4: exclusive scan of NB partials (single block)
__global__ void scan2_kernel() {
    __shared__ int sh[512];
    int tid = threadIdx.x;
    int v = (tid < NB) ? g_part[tid] : 0;
    sh[tid] = v; __syncthreads();
    for (int off = 1; off < 512; off <<= 1) {
        int t = (tid >= off) ? sh[tid - off] : 0;
        __syncthreads();
        sh[tid] += t; __syncthreads();
    }
    if (tid < NB) g_part[tid] = sh[tid] - v;
}

// ---------------------------------------------------------------------------
// K5: bucket fill — rowptr computed inline, one packed 8B store per edge
// ---------------------------------------------------------------------------
__global__ void fill_kernel(const int* __restrict__ ei, const float* __restrict__ ew) {
    int e = blockIdx.x * blockDim.x + threadIdx.x;
    if (e >= NE) return;
    int src = ei[e];
    int dst = ei[NE + e];
    float nm = g_dinv[src] * ew[e] * g_dinv[dst];
    int pos = g_lscan[dst] + g_part[dst >> 8] + atomicAdd(&g_fill[dst], 1);
    g_edge[pos] = make_int2(src, __float_as_int(nm));
}

// ---------------------------------------------------------------------------
// K6: h = x @ (W1*M1) via mma.sync bf16 2-term hi/lo split. Output fp16.
// ---------------------------------------------------------------------------
#define MBLK 128
#define XST 72                       // smem row stride (bf16 elems) = 144 B
#define OFF_XH 0
#define OFF_XL (MBLK * XST)
#define OFF_WH (OFF_XL + MBLK * XST)
#define OFF_WL (OFF_WH + 64 * XST)
#define SMEM_ELEMS (OFF_WL + 64 * XST)
#define SMEM_BYTES (SMEM_ELEMS * 2)

__global__ __launch_bounds__(256) void gemm1_mma(const float* __restrict__ x) {
    extern __shared__ __align__(16) __nv_bfloat16 sm[];
    uint32_t sb = smem_to_u32(sm);
    int tid = threadIdx.x;
    int wid = tid >> 5;
    int lane = tid & 31;
    int brow = blockIdx.x * MBLK;
    int m0 = wid * 16;

    float acc[8][4];
#pragma unroll
    for (int nb = 0; nb < 8; nb++)
#pragma unroll
        for (int j = 0; j < 4; j++) acc[nb][j] = 0.0f;

    for (int kc = 0; kc < NF; kc += 64) {
#pragma unroll
        for (int it = 0; it < 8; it++) {
            int slot = tid + it * 256;
            int r = slot >> 4;
            int q = slot & 15;
            float4 v = make_float4(0.f, 0.f, 0.f, 0.f);
            int grow = brow + r;
            if (grow < NN)
                v = *(const float4*)&x[(size_t)grow * NF + kc + q * 4];
            __nv_bfloat16 hx = __float2bfloat16(v.x), hy = __float2bfloat16(v.y);
            __nv_bfloat16 hz = __float2bfloat16(v.z), hw = __float2bfloat16(v.w);
            __nv_bfloat162 h0; h0.x = hx; h0.y = hy;
            __nv_bfloat162 h1; h1.x = hz; h1.y = hw;
            __nv_bfloat162 l0, l1;
            l0.x = __float2bfloat16(v.x - __bfloat162float(hx));
            l0.y = __float2bfloat16(v.y - __bfloat162float(hy));
            l1.x = __float2bfloat16(v.z - __bfloat162float(hz));
            l1.y = __float2bfloat16(v.w - __bfloat162float(hw));
            *(uint2*)&sm[OFF_XH + r * XST + q * 4] = make_uint2(*(uint32_t*)&h0, *(uint32_t*)&h1);
            *(uint2*)&sm[OFF_XL + r * XST + q * 4] = make_uint2(*(uint32_t*)&l0, *(uint32_t*)&l1);
        }
#pragma unroll
        for (int it = 0; it < 4; it++) {
            int slot = tid + it * 256;
            int r = slot >> 4;
            int q = slot & 15;
            *(uint2*)&sm[OFF_WH + r * XST + q * 4] = *(const uint2*)&g_W1bh[(size_t)(kc + r) * ND + q * 4];
            *(uint2*)&sm[OFF_WL + r * XST + q * 4] = *(const uint2*)&g_W1bl[(size_t)(kc + r) * ND + q * 4];
        }
        __syncthreads();

#pragma unroll
        for (int ks = 0; ks < 4; ks++) {
            int arow = m0 + (lane & 15);
            int acol = ks * 16 + (lane >> 4) * 8;
            uint32_t ah[4], al[4];
            ldm_x4(ah, sb + (OFF_XH + arow * XST + acol) * 2);
            ldm_x4(al, sb + (OFF_XL + arow * XST + acol) * 2);

            int brow_k = ks * 16 + (lane & 15);
#pragma unroll
            for (int nb = 0; nb < 8; nb++) {
                uint32_t bh[2], bl[2];
                ldm_x2t(bh, sb + (OFF_WH + brow_k * XST + nb * 8) * 2);
                ldm_x2t(bl, sb + (OFF_WL + brow_k * XST + nb * 8) * 2);
                mma_bf16(acc[nb], ah, bh);
                mma_bf16(acc[nb], ah, bl);
                mma_bf16(acc[nb], al, bh);
            }
        }
        __syncthreads();
    }

    int r0 = brow + m0 + (lane >> 2);
    int r1 = r0 + 8;
    int cbase = (lane & 3) * 2;
#pragma unroll
    for (int nb = 0; nb < 8; nb++) {
        int col = nb * 8 + cbase;
        if (r0 < NN)
            *(__half2*)&g_h16[(size_t)r0 * ND + col] = __floats2half2_rn(acc[nb][0], acc[nb][1]);
        if (r1 < NN)
            *(__half2*)&g_h16[(size_t)r1 * ND + col] = __floats2half2_rn(acc[nb][2], acc[nb][3]);
    }
}

// ---------------------------------------------------------------------------
// K7: fused gather + relu + classifier. One warp per node, 8-wide MLP unroll.
// ---------------------------------------------------------------------------
__global__ __launch_bounds__(256) void gather_fused_kernel(const float* __restrict__ b1,
                                                           const float* __restrict__ b2,
                                                           float* __restrict__ out) {
    __shared__ float w2t[NC][ND];
    __shared__ float b1s[ND];
    __shared__ float b2s[NC];
    int tid = threadIdx.x;
    for (int k = tid; k < NC * ND; k += 256) ((float*)w2t)[k] = g_Wm2t[k];
    if (tid < ND) b1s[tid] = b1[tid];
    if (tid < NC) b2s[tid] = b2[tid];
    __syncthreads();

    int warp = tid >> 5;
    int lane = tid & 31;
    int i = blockIdx.x * 8 + warp;
    if (i >= NN) return;

    float di = g_dinv[i];
    float sloop = di * di;
    float2 self = __half22float2(((const __half2*)&g_h16[(size_t)i * ND])[lane]);
    float2 acc = make_float2(self.x * sloop, self.y * sloop);

    int beg = g_lscan[i] + g_part[i >> 8];
    int end = beg + g_cnt[i];
    int k = beg;
    for (; k + 7 < end; k += 8) {
        int2 e[8];
#pragma unroll
        for (int u = 0; u < 8; u++) e[u] = g_edge[k + u];
        float2 hv[8];
#pragma unroll
        for (int u = 0; u < 8; u++)
            hv[u] = __half22float2(((const __half2*)&g_h16[(size_t)e[u].x * ND])[lane]);
#pragma unroll
        for (int u = 0; u < 8; u++) {
            float n = __int_as_float(e[u].y);
            acc.x += hv[u].x * n;
            acc.y += hv[u].y * n;
        }
    }
    for (; k < end; k++) {
        int2 e0 = g_edge[k];
        float2 h0 = __half22float2(((const __half2*)&g_h16[(size_t)e0.x * ND])[lane]);
        float n0 = __int_as_float(e0.y);
        acc.x += h0.x * n0;
        acc.y += h0.y * n0;
    }

    float zx = fmaxf(acc.x + b1s[lane * 2],     0.f);
    float zy = fmaxf(acc.y + b1s[lane * 2 + 1], 0.f);

    float p[NC];
#pragma unroll
    for (int c = 0; c < NC; c++)
        p[c] = zx * w2t[c][lane * 2] + zy * w2t[c][lane * 2 + 1];
#pragma unroll
    for (int off = 16; off > 0; off >>= 1)
#pragma unroll
        for (int c = 0; c < NC; c++)
            p[c] += __shfl_down_sync(0xFFFFFFFFu, p[c], off);

    if (lane == 0) {
#pragma unroll
        for (int c = 0; c < NC; c++)
            out[(size_t)i * NC + c] = p[c] + b2s[c];
    }
}

// ---------------------------------------------------------------------------
// launch: 0:x 1:edge_index 2:edge_weight 3:W1 4:M1 5:b1 6:W2 7:M2 8:b2
// gemm1 forked onto a side stream (capture-safe event fork/join) to overlap
// with the atomic-bound graph pipeline.
// ---------------------------------------------------------------------------
extern "C" void kernel_launch(void* const* d_in, const int* in_sizes, int n_in,
                              void* d_out, int out_size) {
    const float* x  = (const float*)d_in[0];
    const int*   ei = (const int*)d_in[1];
    const float* ew = (const float*)d_in[2];
    const float* W1 = (const float*)d_in[3];
    const float* M1 = (const float*)d_in[4];
    const float* b1 = (const float*)d_in[5];
    const float* W2 = (const float*)d_in[6];
    const float* M2 = (const float*)d_in[7];
    const float* b2 = (const float*)d_in[8];
    float* out = (float*)d_out;

    cudaFuncSetAttribute(gemm1_mma, cudaFuncAttributeMaxDynamicSharedMemorySize, SMEM_BYTES);

    // host-side resources (no device memory); harness calls this only a few
    // times, so the un-destroyed handles are a bounded host-side leak.
    cudaStream_t s2;
    cudaEvent_t ev1, ev2;
    cudaStreamCreateWithFlags(&s2, cudaStreamNonBlocking);
    cudaEventCreateWithFlags(&ev1, cudaEventDisableTiming);
    cudaEventCreateWithFlags(&ev2, cudaEventDisableTiming);

    prep_kernel<<<NB, 256>>>(W1, M1, W2, M2);
    cudaEventRecord(ev1, 0);

    count_deg_kernel<<<NE / 256, 256>>>(ei, ew);

    cudaStreamWaitEvent(s2, ev1, 0);
    gemm1_mma<<<(NN + MBLK - 1) / MBLK, 256, SMEM_BYTES, s2>>>(x);
    cudaEventRecord(ev2, s2);

    dinv_scan1_kernel<<<NB, 256>>>();
    scan2_kernel<<<1, 512>>>();
    fill_kernel<<<NE / 256, 256>>>(ei, ew);

    cudaStreamWaitEvent(0, ev2, 0);
    gather_fused_kernel<<<(NN + 7) / 8, 256>>>(b1, b2, out);
}

// round 14
// speedup vs baseline: 1.7767x; 1.0626x over previous
#include <cuda_runtime.h>
#include <cuda_bf16.h>
#include <cuda_fp16.h>
#include <stdint.h>

#define NN 100000
#define NE 3200000
#define NF 512
#define ND 64
#define NC 10
#define NB 391          // ceil(NN/256) scan blocks
#define PACK 1048576.0  // 2^20: count packed above this in double

// ---- scratch (no allocations allowed; BSS-zeroed at load, re-zeroed by tail) ----
__device__ __align__(16) __half g_h16[(size_t)NN * ND];  // 12.8 MB
__device__ double g_dpack[NN];                            // deg + cnt*2^20
__device__ float g_dinv[NN];
__device__ int   g_cnt[NN];
__device__ int   g_fill[NN];
__device__ int   g_lscan[NN];
__device__ int   g_part[512];
__device__ unsigned int g_done;
__device__ __align__(16) int2 g_edge[NE];                 // (src, norm-bits) 25.6 MB
__device__ __align__(16) __nv_bfloat16 g_W1bh[NF * ND];   // [k][n] bf16 hi
__device__ __align__(16) __nv_bfloat16 g_W1bl[NF * ND];   // [k][n] bf16 lo
__device__ __align__(16) float g_Wm2t[NC * ND];           // [c][j]

// ===========================================================================
// warp-MMA helpers (baseline PTX: works on plain sm_103 target)
// ===========================================================================
__device__ __forceinline__ uint32_t smem_to_u32(const void* p) {
    uint32_t a;
    asm("{ .reg .u64 t; cvta.to.shared.u64 t, %1; cvt.u32.u64 %0, t; }" : "=r"(a) : "l"(p));
    return a;
}
__device__ __forceinline__ void ldm_x4(uint32_t* r, uint32_t a) {
    asm volatile("ldmatrix.sync.aligned.m8n8.x4.shared.b16 {%0,%1,%2,%3}, [%4];"
                 : "=r"(r[0]), "=r"(r[1]), "=r"(r[2]), "=r"(r[3]) : "r"(a));
}
__device__ __forceinline__ void ldm_x2t(uint32_t* r, uint32_t a) {
    asm volatile("ldmatrix.sync.aligned.m8n8.x2.trans.shared.b16 {%0,%1}, [%2];"
                 : "=r"(r[0]), "=r"(r[1]) : "r"(a));
}
__device__ __forceinline__ void mma_bf16(float* c, const uint32_t* a, const uint32_t* b) {
    asm volatile("mma.sync.aligned.m16n8k16.row.col.f32.bf16.bf16.f32 "
                 "{%0,%1,%2,%3}, {%4,%5,%6,%7}, {%8,%9}, {%0,%1,%2,%3};"
                 : "+f"(c[0]), "+f"(c[1]), "+f"(c[2]), "+f"(c[3])
                 : "r"(a[0]), "r"(a[1]), "r"(a[2]), "r"(a[3]), "r"(b[0]), "r"(b[1]));
}

// ---------------------------------------------------------------------------
// K-A (launch #1): packed degree+count — single double atomic per edge
// ---------------------------------------------------------------------------
__global__ void count_deg_kernel(const int* __restrict__ ei, const float* __restrict__ ew) {
    int e = blockIdx.x * blockDim.x + threadIdx.x;
    if (e >= NE) return;
    int dst = ei[NE + e];
    atomicAdd(&g_dpack[dst], (double)ew[e] + PACK);
}

// ---------------------------------------------------------------------------
// K-B (#2): unpack cnt/deg -> dinv, block-local scan, fused global scan of
// partials via last-block-done pattern.
// ---------------------------------------------------------------------------
__global__ void dinv_scan_kernel() {
    __shared__ int sh[256];
    __shared__ bool last;
    int tid = threadIdx.x;
    int i = blockIdx.x * 256 + tid;
    int c = 0;
    if (i < NN) {
        double dp = g_dpack[i];
        c = (int)(dp * (1.0 / PACK));
        float deg = (float)(dp - (double)c * PACK);
        g_cnt[i] = c;
        g_dinv[i] = rsqrtf(deg + 1.0f);
    }
    sh[tid] = c; __syncthreads();
    for (int off = 1; off < 256; off <<= 1) {
        int t = (tid >= off) ? sh[tid - off] : 0;
        __syncthreads();
        sh[tid] += t; __syncthreads();
    }
    if (i < NN) g_lscan[i] = sh[tid] - c;          // block-local exclusive
    if (tid == 255) g_part[blockIdx.x] = sh[255];
    __threadfence();
    if (tid == 0) {
        unsigned int old = atomicAdd(&g_done, 1u);
        last = (old == (unsigned int)gridDim.x - 1u);
    }
    __syncthreads();
    if (last && tid < 32) {                        // warp 0 scans the partials
        int run = 0;
        for (int cb = 0; cb < (NB + 31) / 32; cb++) {
            int idx = cb * 32 + tid;
            int v = (idx < NB) ? g_part[idx] : 0;
            int xv = v;
#pragma unroll
            for (int o = 1; o < 32; o <<= 1) {
                int t = __shfl_up_sync(0xFFFFFFFFu, xv, o);
                if (tid >= o) xv += t;
            }
            if (idx < NB) g_part[idx] = xv - v + run;   // exclusive + offset
            run += __shfl_sync(0xFFFFFFFFu, xv, 31);
        }
    }
}

// ---------------------------------------------------------------------------
// K-C (s2): W1 bf16 hi/lo split + W2 mask/transpose (no zeroing)
// ---------------------------------------------------------------------------
__global__ void prep_w_kernel(const float* __restrict__ W1, const float* __restrict__ M1,
                              const float* __restrict__ W2, const float* __restrict__ M2) {
    int idx = blockIdx.x * blockDim.x + threadIdx.x;
    if (idx < NF * ND) {
        float w = W1[idx] * M1[idx];
        __nv_bfloat16 hi = __float2bfloat16(w);
        float r = w - __bfloat162float(hi);
        g_W1bh[idx] = hi;
        g_W1bl[idx] = __float2bfloat16(r);
    }
    if (idx < ND * NC) {
        int j = idx / NC, c = idx % NC;
        g_Wm2t[c * ND + j] = W2[idx] * M2[idx];
    }
}

// ---------------------------------------------------------------------------
// K-D (#4): bucket fill — rowptr inline, one packed 8B store per edge
// ---------------------------------------------------------------------------
__global__ void fill_kernel(const int* __restrict__ ei, const float* __restrict__ ew) {
    int e = blockIdx.x * blockDim.x + threadIdx.x;
    if (e >= NE) return;
    int src = ei[e];
    int dst = ei[NE + e];
    float nm = g_dinv[src] * ew[e] * g_dinv[dst];
    int pos = g_lscan[dst] + g_part[dst >> 8] + atomicAdd(&g_fill[dst], 1);
    g_edge[pos] = make_int2(src, __float_as_int(nm));
}

// ---------------------------------------------------------------------------
// K-E (s2): h = x @ (W1*M1) via mma.sync bf16 hi/lo split. Output fp16.
// ---------------------------------------------------------------------------
#define MBLK 128
#define XST 72
#define OFF_XH 0
#define OFF_XL (MBLK * XST)
#define OFF_WH (OFF_XL + MBLK * XST)
#define OFF_WL (OFF_WH + 64 * XST)
#define SMEM_ELEMS (OFF_WL + 64 * XST)
#define SMEM_BYTES (SMEM_ELEMS * 2)

__global__ __launch_bounds__(256) void gemm1_mma(const float* __restrict__ x) {
    extern __shared__ __align__(16) __nv_bfloat16 sm[];
    uint32_t sb = smem_to_u32(sm);
    int tid = threadIdx.x;
    int wid = tid >> 5;
    int lane = tid & 31;
    int brow = blockIdx.x * MBLK;
    int m0 = wid * 16;

    float acc[8][4];
#pragma unroll
    for (int nb = 0; nb < 8; nb++)
#pragma unroll
        for (int j = 0; j < 4; j++) acc[nb][j] = 0.0f;

    for (int kc = 0; kc < NF; kc += 64) {
#pragma unroll
        for (int it = 0; it < 8; it++) {
            int slot = tid + it * 256;
            int r = slot >> 4;
            int q = slot & 15;
            float4 v = make_float4(0.f, 0.f, 0.f, 0.f);
            int grow = brow + r;
            if (grow < NN)
                v = *(const float4*)&x[(size_t)grow * NF + kc + q * 4];
            __nv_bfloat16 hx = __float2bfloat16(v.x), hy = __float2bfloat16(v.y);
            __nv_bfloat16 hz = __float2bfloat16(v.z), hw = __float2bfloat16(v.w);
            __nv_bfloat162 h0; h0.x = hx; h0.y = hy;
            __nv_bfloat162 h1; h1.x = hz; h1.y = hw;
            __nv_bfloat162 l0, l1;
            l0.x = __float2bfloat16(v.x - __bfloat162float(hx));
            l0.y = __float2bfloat16(v.y - __bfloat162float(hy));
            l1.x = __float2bfloat16(v.z - __bfloat162float(hz));
            l1.y = __float2bfloat16(v.w - __bfloat162float(hw));
            *(uint2*)&sm[OFF_XH + r * XST + q * 4] = make_uint2(*(uint32_t*)&h0, *(uint32_t*)&h1);
            *(uint2*)&sm[OFF_XL + r * XST + q * 4] = make_uint2(*(uint32_t*)&l0, *(uint32_t*)&l1);
        }
#pragma unroll
        for (int it = 0; it < 4; it++) {
            int slot = tid + it * 256;
            int r = slot >> 4;
            int q = slot & 15;
            *(uint2*)&sm[OFF_WH + r * XST + q * 4] = *(const uint2*)&g_W1bh[(size_t)(kc + r) * ND + q * 4];
            *(uint2*)&sm[OFF_WL + r * XST + q * 4] = *(const uint2*)&g_W1bl[(size_t)(kc + r) * ND + q * 4];
        }
        __syncthreads();

#pragma unroll
        for (int ks = 0; ks < 4; ks++) {
            int arow = m0 + (lane & 15);
            int acol = ks * 16 + (lane >> 4) * 8;
            uint32_t ah[4], al[4];
            ldm_x4(ah, sb + (OFF_XH + arow * XST + acol) * 2);
            ldm_x4(al, sb + (OFF_XL + arow * XST + acol) * 2);

            int brow_k = ks * 16 + (lane & 15);
#pragma unroll
            for (int nb = 0; nb < 8; nb++) {
                uint32_t bh[2], bl[2];
                ldm_x2t(bh, sb + (OFF_WH + brow_k * XST + nb * 8) * 2);
                ldm_x2t(bl, sb + (OFF_WL + brow_k * XST + nb * 8) * 2);
                mma_bf16(acc[nb], ah, bh);
                mma_bf16(acc[nb], ah, bl);
                mma_bf16(acc[nb], al, bh);
            }
        }
        __syncthreads();
    }

    int r0 = brow + m0 + (lane >> 2);
    int r1 = r0 + 8;
    int cbase = (lane & 3) * 2;
#pragma unroll
    for (int nb = 0; nb < 8; nb++) {
        int col = nb * 8 + cbase;
        if (r0 < NN)
            *(__half2*)&g_h16[(size_t)r0 * ND + col] = __floats2half2_rn(acc[nb][0], acc[nb][1]);
        if (r1 < NN)
            *(__half2*)&g_h16[(size_t)r1 * ND + col] = __floats2half2_rn(acc[nb][2], acc[nb][3]);
    }
}

// ---------------------------------------------------------------------------
// K-F: fused gather + relu + classifier. One warp per node, MLP-8.
// ---------------------------------------------------------------------------
__global__ __launch_bounds__(256) void gather_fused_kernel(const float* __restrict__ b1,
                                                           const float* __restrict__ b2,
                                                           float* __restrict__ out) {
    __shared__ float w2t[NC][ND];
    __shared__ float b1s[ND];
    __shared__ float b2s[NC];
    int tid = threadIdx.x;
    for (int k = tid; k < NC * ND; k += 256) ((float*)w2t)[k] = g_Wm2t[k];
    if (tid < ND) b1s[tid] = b1[tid];
    if (tid < NC) b2s[tid] = b2[tid];
    __syncthreads();

    int warp = tid >> 5;
    int lane = tid & 31;
    int i = blockIdx.x * 8 + warp;
    if (i >= NN) return;

    float di = g_dinv[i];
    float sloop = di * di;
    float2 self = __half22float2(((const __half2*)&g_h16[(size_t)i * ND])[lane]);
    float2 acc = make_float2(self.x * sloop, self.y * sloop);

    int beg = g_lscan[i] + g_part[i >> 8];
    int end = beg + g_cnt[i];
    int k = beg;
    for (; k + 7 < end; k += 8) {
        int2 e[8];
#pragma unroll
        for (int u = 0; u < 8; u++) e[u] = g_edge[k + u];
        float2 hv[8];
#pragma unroll
        for (int u = 0; u < 8; u++)
            hv[u] = __half22float2(((const __half2*)&g_h16[(size_t)e[u].x * ND])[lane]);
#pragma unroll
        for (int u = 0; u < 8; u++) {
            float n = __int_as_float(e[u].y);
            acc.x += hv[u].x * n;
            acc.y += hv[u].y * n;
        }
    }
    for (; k < end; k++) {
        int2 e0 = g_edge[k];
        float2 h0 = __half22float2(((const __half2*)&g_h16[(size_t)e0.x * ND])[lane]);
        float n0 = __int_as_float(e0.y);
        acc.x += h0.x * n0;
        acc.y += h0.y * n0;
    }

    float zx = fmaxf(acc.x + b1s[lane * 2],     0.f);
    float zy = fmaxf(acc.y + b1s[lane * 2 + 1], 0.f);

    float p[NC];
#pragma unroll
    for (int c = 0; c < NC; c++)
        p[c] = zx * w2t[c][lane * 2] + zy * w2t[c][lane * 2 + 1];
#pragma unroll
    for (int off = 16; off > 0; off >>= 1)
#pragma unroll
        for (int c = 0; c < NC; c++)
            p[c] += __shfl_down_sync(0xFFFFFFFFu, p[c], off);

    if (lane == 0) {
#pragma unroll
        for (int c = 0; c < NC; c++)
            out[(size_t)i * NC + c] = p[c] + b2s[c];
    }
}

// ---------------------------------------------------------------------------
// K-G: tail zero for next replay (first call relies on BSS zero-init)
// ---------------------------------------------------------------------------
__global__ void zero_tail_kernel() {
    int i = blockIdx.x * blockDim.x + threadIdx.x;
    if (i < NN) { g_dpack[i] = 0.0; g_fill[i] = 0; }
    if (i == 0) g_done = 0u;
}

// ---------------------------------------------------------------------------
// launch: 0:x 1:edge_index 2:edge_weight 3:W1 4:M1 5:b1 6:W2 7:M2 8:b2
// s2 enters capture via event fork from stream 0 (capture-legal), joins
// before gather.
// ---------------------------------------------------------------------------
extern "C" void kernel_launch(void* const* d_in, const int* in_sizes, int n_in,
                              void* d_out, int out_size) {
    const float* x  = (const float*)d_in[0];
    const int*   ei = (const int*)d_in[1];
    const float* ew = (const float*)d_in[2];
    const float* W1 = (const float*)d_in[3];
    const float* M1 = (const float*)d_in[4];
    const float* b1 = (const float*)d_in[5];
    const float* W2 = (const float*)d_in[6];
    const float* M2 = (const float*)d_in[7];
    const float* b2 = (const float*)d_in[8];
    float* out = (float*)d_out;

    cudaFuncSetAttribute(gemm1_mma, cudaFuncAttributeMaxDynamicSharedMemorySize, SMEM_BYTES);

    cudaStream_t s2;
    cudaEvent_t ev0, ev2;
    cudaStreamCreateWithFlags(&s2, cudaStreamNonBlocking);
    cudaEventCreateWithFlags(&ev0, cudaEventDisableTiming);
    cudaEventCreateWithFlags(&ev2, cudaEventDisableTiming);

    // #1: edge atomics on main stream
    count_deg_kernel<<<NE / 256, 256>>>(ei, ew);
    cudaEventRecord(ev0, 0);                      // fork point (capture-legal)

    // side stream: W prep + GEMM (independent of graph pipeline)
    cudaStreamWaitEvent(s2, ev0, 0);
    prep_w_kernel<<<(NF * ND + 255) / 256, 256, 0, s2>>>(W1, M1, W2, M2);
    gemm1_mma<<<(NN + MBLK - 1) / MBLK, 256, SMEM_BYTES, s2>>>(x);
    cudaEventRecord(ev2, s2);

    // main stream continues
    dinv_scan_kernel<<<NB, 256>>>();              // #2 main
    fill_kernel<<<NE / 256, 256>>>(ei, ew);       // #4 overall -> ncu slot
    cudaStreamWaitEvent(0, ev2, 0);               // join
    gather_fused_kernel<<<(NN + 7) / 8, 256>>>(b1, b2, out);
    zero_tail_kernel<<<NB, 256>>>();
}